// round 15
// baseline (speedup 1.0000x reference)
#include <cuda_runtime.h>
#include <cuda_fp16.h>
#include <cstdint>

#define Bv 128
#define Tv 4096
#define DIN 64
#define Hv 512
#define DOUT 64
#define NCTA 128
#define NSTR 4              // independent batch streams per CTA
#define NTHR 384            // 8 compute warps (2/stream) + 4 producer warps
#define K1 576
#define K2 1024
#define K1PH 584            // weight row stride (halfs) -> conflict-free B-frag LDS
#define K2PH 1032
#define NBIG1 5             // L1: 1 x quarter-chunk + 4 big h-chunks
#define NBIG2 8             // L2: 8 big chunks
#define NRING 4             // per-stream ring of big buffers
#define H1D 8               // h1 ring depth (power of 2)
#define GW 72               // row stride (halfs) -> conflict-free A-frag LDS
#define QC_W (32 * GW)      // quarter-chunk (32 rows) in halfs = 2304
#define QC_BYTES (QC_W * 2)         // 4608
#define BIGQ_W (2 * QC_W)           // big chunk (128 k-values, one stream)
#define BIGQ_BYTES (2 * QC_BYTES)   // 9216
#define OW 68               // out_gemm smem stride (floats)
#define FLG 64              // flag spacing (words) = 256B
#define SMEM_BYTES (NSTR * NRING * BIGQ_BYTES + 32 * K2PH * 2 + 128 * 8 * 4 + 32 * 4 + 320)

// Persistent scratch (static __device__: the sanctioned allocation path)
__device__ __half g_xT[(size_t)Tv * NSTR * QC_W];                // x: [t][s][32][GW]
__device__ __half g_h1[H1D][NSTR][8][32][GW];                    // h1 ring, stream-major
__device__ __half g_h2all[(size_t)(Tv + 1) * NSTR * 8 * QC_W];   // h2: [t][s][ch][32][GW]
__device__ unsigned g_flag[NCTA * NSTR * FLG];                   // per-CTA-per-stream flags

__device__ __forceinline__ float sigm(float x) { return 1.0f / (1.0f + __expf(-x)); }
__device__ __forceinline__ float tanh_(float x) { return 1.0f - 2.0f / (__expf(2.0f * x) + 1.0f); }

__device__ __forceinline__ unsigned ld_acq(const unsigned* p) {
    unsigned v;
    asm volatile("ld.acquire.gpu.global.b32 %0, [%1];" : "=r"(v) : "l"(p));
    return v;
}
__device__ __forceinline__ void st_rel(unsigned* p, unsigned v) {
    asm volatile("st.release.gpu.global.b32 [%0], %1;" :: "l"(p), "r"(v) : "memory");
}
__device__ __forceinline__ void flag_spin(const unsigned* p, unsigned tgt) {
    while ((int)(ld_acq(p) - tgt) < 0) {}
}
__device__ __forceinline__ void issue_big(unsigned sdst, const void* gsrc, unsigned mbar,
                                          unsigned bytes) {
    asm volatile("mbarrier.arrive.expect_tx.shared.b64 _, [%0], %1;"
                 :: "r"(mbar), "r"(bytes) : "memory");
    asm volatile("cp.async.bulk.shared::cta.global.mbarrier::complete_tx::bytes [%0], [%1], %2, [%3];"
                 :: "r"(sdst), "l"(gsrc), "r"(bytes), "r"(mbar) : "memory");
}
__device__ __forceinline__ void mbar_wait(unsigned mbar, unsigned parity) {
    asm volatile(
        "{\n\t.reg .pred P;\n"
        "W%=:\n\t"
        "mbarrier.try_wait.parity.acquire.cta.shared::cta.b64 P, [%0], %1, 0x989680;\n\t"
        "@!P bra W%=;\n\t}"
        :: "r"(mbar), "r"(parity) : "memory");
}
__device__ __forceinline__ void mbar_arrive(unsigned mbar) {
    asm volatile("mbarrier.arrive.shared.b64 _, [%0];" :: "r"(mbar) : "memory");
}

// One-time x transpose + fp16 round: x[b][t][64] -> xT[t][stream][32][GW]
__global__ void __launch_bounds__(256)
xpose(const float* __restrict__ x) {
    const int t = blockIdx.x;
    for (int i = threadIdx.x; i < 128 * 16; i += 256) {
        int b = i >> 4, j = i & 15;
        int s = b >> 5, lr = b & 31;
        float4 v = *(const float4*)(x + ((size_t)b * Tv + t) * 64 + j * 4);
        __half2* dst = (__half2*)(g_xT + ((size_t)t * NSTR + s) * QC_W + lr * GW + j * 4);
        dst[0] = __floats2half2_rn(v.x, v.y);
        dst[1] = __floats2half2_rn(v.z, v.w);
    }
}

__global__ void __launch_bounds__(NTHR, 1)
lstm_kernel(const float* __restrict__ w_ih1, const float* __restrict__ w_hh1,
            const float* __restrict__ b_ih1, const float* __restrict__ b_hh1,
            const float* __restrict__ w_ih2, const float* __restrict__ w_hh2,
            const float* __restrict__ b_ih2, const float* __restrict__ b_hh2) {
    extern __shared__ __half smh[];
    __half* swh = smh + NSTR * NRING * BIGQ_W;       // weights fp16 [32][K1PH|K2PH]
    float* sc = (float*)(swh + 32 * K2PH);           // c-state [128][8] (global row)
    float* sb = sc + 128 * 8;                        // fused biases [32]
    float* mbf = sb + 32;                            // full[16]@+0 (128B), consumed[16]@+128
    __shared__ unsigned s_e0[NSTR];

    const int tid = threadIdx.x;
    const bool isL2 = blockIdx.x >= 64;
    const int cl = blockIdx.x & 63;
    const int u0 = cl * 8;
    const int lane = tid & 31, warp = tid >> 5;
    const int c4 = lane & 3, q = lane >> 2;
    const int KPH = isL2 ? K2PH : K1PH;
    const int NBIG = isL2 ? NBIG2 : NBIG1;
    const unsigned smem_base = (unsigned)__cvta_generic_to_shared(smh);
    const unsigned mb = (unsigned)__cvta_generic_to_shared(mbf);
    const int ch = u0 >> 6, colbase = u0 & 63;

    if (tid == 0) {
#pragma unroll
        for (int s = 0; s < NSTR; s++)
            s_e0[s] = ld_acq(&g_flag[(blockIdx.x * NSTR + s) * FLG]);
#pragma unroll
        for (int b = 0; b < NSTR * NRING; b++) {
            asm volatile("mbarrier.init.shared.b64 [%0], 1;" :: "r"(mb + b * 8) : "memory");
            asm volatile("mbarrier.init.shared.b64 [%0], 2;" :: "r"(mb + 128 + b * 8) : "memory");
        }
        asm volatile("fence.proxy.async.shared::cta;" ::: "memory");
    }

    // ---- stage weight slice (fp16) + fused biases ----
    if (!isL2) {
        for (int idx = tid; idx < 32 * K1; idx += NTHR) {
            int r = idx / K1, k = idx - r * K1;
            int j = (r >> 3) * Hv + u0 + (r & 7);
            float wv = (k < DIN) ? w_ih1[j * DIN + k] : w_hh1[(size_t)j * Hv + (k - DIN)];
            swh[r * K1PH + k] = __float2half_rn(wv);
        }
        if (tid < 32) {
            int j = (tid >> 3) * Hv + u0 + (tid & 7);
            sb[tid] = b_ih1[j] + b_hh1[j];
        }
    } else {
        for (int idx = tid; idx < 32 * K2; idx += NTHR) {
            int r = idx >> 10, k = idx & 1023;
            int j = (r >> 3) * Hv + u0 + (r & 7);
            float wv = (k < Hv) ? w_ih2[(size_t)j * Hv + k] : w_hh2[(size_t)j * Hv + (k - Hv)];
            swh[r * K2PH + k] = __float2half_rn(wv);
        }
        if (tid < 32) {
            int j = (tid >> 3) * Hv + u0 + (tid & 7);
            sb[tid] = b_ih2[j] + b_hh2[j];
        }
    }
    for (int i = tid; i < 128 * 8; i += NTHR) sc[i] = 0.0f;

    // ---- zero OWN slice of initial state: h1 ring slot H1D-1 / h2 slot 0 ----
    if (tid < 128) {
        __half z[8];
#pragma unroll
        for (int i = 0; i < 8; i++) z[i] = __float2half(0.0f);
        int s = tid >> 5, lr = tid & 31;
        __half* dst = isL2
            ? g_h2all + (size_t)s * 8 * QC_W + ch * QC_W + lr * GW + colbase
            : &g_h1[H1D - 1][s][ch][lr][colbase];
        *(uint4*)dst = *(const uint4*)z;
    }
    __syncthreads();
    if (tid == 0) {
        __threadfence();
#pragma unroll
        for (int s = 0; s < NSTR; s++)
            st_rel(&g_flag[(blockIdx.x * NSTR + s) * FLG], s_e0[s] + 1);
    }
    __syncthreads();   // all threads see s_e0

    if (warp >= 8) {
        // ================= PRODUCER WARPS (8-11: streams 0-3) =================
        const int s = warp - 8;
        const unsigned E0 = s_e0[s];
        const unsigned fullb0 = mb + s * NRING * 8;
        const unsigned consb0 = mb + 128 + s * NRING * 8;
        const unsigned cbase = smem_base + s * NRING * BIGQ_BYTES;
        unsigned gidx = 0;
        for (int p = 0; p <= Tv; p++) {
            const bool active = isL2 ? (p >= 1) : (p < Tv);
            if (!active) continue;
            const unsigned T = E0 + (unsigned)p + 1u;
            if (!isL2 && p >= 6) {   // slack: keep L1 bounded ahead of L2 (own stream)
                const unsigned ts = E0 + (unsigned)p - 5u;
                for (int k = lane; k < 64; k += 32)
                    flag_spin(&g_flag[((64 + k) * NSTR + s) * FLG], ts);
                __syncwarp();
            }
            const __half* srcA;
            const __half* srcB;
            if (isL2) {
                srcA = &g_h1[(p - 1) & (H1D - 1)][s][0][0][0];
                srcB = g_h2all + ((size_t)(p - 1) * NSTR + s) * 8 * QC_W;
            } else {
                srcA = g_xT + ((size_t)p * NSTR + s) * QC_W;
                srcB = &g_h1[(p - 1) & (H1D - 1)][s][0][0][0];
            }
            for (int b = 0; b < NBIG; b++) {
                const __half* src;
                unsigned bytes;
                int pbase = -1;
                if (!isL2) {
                    if (b == 0) { src = srcA; bytes = QC_BYTES; }
                    else { src = srcB + (size_t)(b - 1) * BIGQ_W; bytes = BIGQ_BYTES;
                           pbase = (b - 1) * 16; }
                } else {
                    bytes = BIGQ_BYTES;
                    if (b < 4) { src = srcA + (size_t)b * BIGQ_W; pbase = b * 16; }
                    else { src = srcB + (size_t)(b - 4) * BIGQ_W; pbase = 64 + (b - 4) * 16; }
                }
                if (pbase >= 0) {
                    if (lane < 16) flag_spin(&g_flag[((pbase + lane) * NSTR + s) * FLG], T);
                    __syncwarp();
                }
                const unsigned sl = gidx & (NRING - 1), m = gidx >> 2;
                if (lane == 0) {
                    if (m >= 1) mbar_wait(consb0 + sl * 8, (m - 1) & 1u);
                    issue_big(cbase + sl * BIGQ_BYTES, src, fullb0 + sl * 8, bytes);
                }
                __syncwarp();
                gidx++;
            }
        }
    } else {
        // ================= COMPUTE WARPS: warp w -> stream w>>1 =================
        const int s = warp >> 1;
        const unsigned E0 = s_e0[s];
        const int wl = warp & 1;
        const int r0 = wl * 16 + q, r1 = r0 + 8;     // rows within 32-row quarter
        const unsigned fullb0 = mb + s * NRING * 8;
        const unsigned consb0 = mb + 128 + s * NRING * 8;
        __half* chunks = smh + s * NRING * BIGQ_W;
        unsigned* myflag = &g_flag[(blockIdx.x * NSTR + s) * FLG];
        unsigned phbits = 0, gidx = 0;
        for (int p = 0; p <= Tv; p++) {
            const bool active = isL2 ? (p >= 1) : (p < Tv);
            if (active) {
                float acc[4][4];
#pragma unroll
                for (int g = 0; g < 4; g++) {
                    float b0 = sb[g * 8 + 2 * c4], b1 = sb[g * 8 + 2 * c4 + 1];
                    acc[g][0] = b0; acc[g][1] = b1; acc[g][2] = b0; acc[g][3] = b1;
                }
                for (int b = 0; b < NBIG; b++) {
                    const unsigned sl = gidx & (NRING - 1);
                    mbar_wait(fullb0 + sl * 8, (phbits >> sl) & 1u);
                    phbits ^= (1u << sl);

                    const int nsub = (isL2 || b > 0) ? 2 : 1;
                    const int kbb = isL2 ? b * 128 : (b == 0 ? 0 : 64 + (b - 1) * 128);
                    for (int s2 = 0; s2 < nsub; s2++) {
                        const __half* ar0 = chunks + sl * BIGQ_W + s2 * QC_W
                                          + r0 * GW + 2 * c4;
                        const __half* ar1 = chunks + sl * BIGQ_W + s2 * QC_W
                                          + r1 * GW + 2 * c4;
                        const int kb = kbb + s2 * 64;
#pragma unroll
                        for (int kc = 0; kc < 64; kc += 16) {
                            unsigned a0 = *(const unsigned*)(ar0 + kc);
                            unsigned a1 = *(const unsigned*)(ar1 + kc);
                            unsigned a2 = *(const unsigned*)(ar0 + kc + 8);
                            unsigned a3 = *(const unsigned*)(ar1 + kc + 8);
#pragma unroll
                            for (int g = 0; g < 4; g++) {
                                const __half* bp = swh + (g * 8 + q) * KPH + kb + kc + 2 * c4;
                                unsigned b0 = *(const unsigned*)bp;
                                unsigned b1 = *(const unsigned*)(bp + 8);
                                asm volatile(
                                    "mma.sync.aligned.m16n8k16.row.col.f32.f16.f16.f32 "
                                    "{%0,%1,%2,%3},{%4,%5,%6,%7},{%8,%9},{%0,%1,%2,%3};"
                                    : "+f"(acc[g][0]), "+f"(acc[g][1]),
                                      "+f"(acc[g][2]), "+f"(acc[g][3])
                                    : "r"(a0), "r"(a1), "r"(a2), "r"(a3), "r"(b0), "r"(b1));
                            }
                        }
                    }
                    if (lane == 0) mbar_arrive(consb0 + sl * 8);
                    gidx++;
                }

                // ---- epilogue: nonlinearities, c update (SMEM), fp16 h store ----
                __half* hout = isL2
                    ? g_h2all + ((size_t)p * NSTR + s) * 8 * QC_W + ch * QC_W + colbase
                    : &g_h1[p & (H1D - 1)][s][ch][0][colbase];
#pragma unroll
                for (int jj = 0; jj < 2; jj++) {
                    int ul = 2 * c4 + jj;
#pragma unroll
                    for (int rr = 0; rr < 2; rr++) {
                        int lr = rr ? r1 : r0;
                        int qi = rr * 2 + jj;
                        float iv = sigm(acc[0][qi]);
                        float fv = sigm(acc[1][qi]);
                        float gv = tanh_(acc[2][qi]);
                        float ov = sigm(acc[3][qi]);
                        int grow = s * 32 + lr;
                        float cn = fv * sc[grow * 8 + ul] + iv * gv;
                        sc[grow * 8 + ul] = cn;
                        hout[(size_t)lr * GW + ul] = __float2half_rn(ov * tanh_(cn));
                    }
                }
            }
            // per-stream compute barrier (64 threads), then publish stream flag
            asm volatile("bar.sync %0, 64;" :: "r"(s + 1) : "memory");
            if (wl == 0 && lane == 0) {
                __threadfence();
                st_rel(myflag, E0 + (unsigned)p + 2u);
            }
        }
    }
}

// Post-pass: out[b][t][o] = h2(t)[b] . w_out[o] + b_out[o]
__global__ void __launch_bounds__(256)
out_gemm(const float* __restrict__ w_out, const float* __restrict__ b_out,
         float* __restrict__ out) {
    __shared__ __align__(16) float As[32 * OW];  // [k][t]
    __shared__ __align__(16) float Bs[32 * OW];  // [k][o]
    const int b = blockIdx.y;
    const int t0 = blockIdx.x * 64;
    const int tx = threadIdx.x;
    const int to = (tx & 15) * 4;
    const int tt = (tx >> 4) * 4;
    const int bs = b >> 5, blr = b & 31;
    float acc[4][4] = {};
    for (int k0 = 0; k0 < Hv; k0 += 32) {
        for (int i = tx; i < 512; i += 256) {
            int row = i >> 3, kq = (i & 7) * 4;
            const __half* src = g_h2all + ((size_t)(t0 + row + 1) * NSTR + bs) * 8 * QC_W
                              + (k0 >> 6) * QC_W + (size_t)blr * GW + (k0 & 63) + kq;
            float2 f0 = __half22float2(*(const __half2*)(src));
            float2 f1 = __half22float2(*(const __half2*)(src + 2));
            As[(kq + 0) * OW + row] = f0.x;
            As[(kq + 1) * OW + row] = f0.y;
            As[(kq + 2) * OW + row] = f1.x;
            As[(kq + 3) * OW + row] = f1.y;
        }
        for (int i = tx; i < 512; i += 256) {
            int o = i >> 3, kq = (i & 7) * 4;
            float4 v = *(const float4*)(w_out + (size_t)o * Hv + k0 + kq);
            Bs[(kq + 0) * OW + o] = v.x;
            Bs[(kq + 1) * OW + o] = v.y;
            Bs[(kq + 2) * OW + o] = v.z;
            Bs[(kq + 3) * OW + o] = v.w;
        }
        __syncthreads();
#pragma unroll
        for (int k = 0; k < 32; k++) {
            float4 a = *(const float4*)(As + k * OW + tt);
            float4 w = *(const float4*)(Bs + k * OW + to);
            acc[0][0] = fmaf(a.x, w.x, acc[0][0]); acc[0][1] = fmaf(a.x, w.y, acc[0][1]);
            acc[0][2] = fmaf(a.x, w.z, acc[0][2]); acc[0][3] = fmaf(a.x, w.w, acc[0][3]);
            acc[1][0] = fmaf(a.y, w.x, acc[1][0]); acc[1][1] = fmaf(a.y, w.y, acc[1][1]);
            acc[1][2] = fmaf(a.y, w.z, acc[1][2]); acc[1][3] = fmaf(a.y, w.w, acc[1][3]);
            acc[2][0] = fmaf(a.z, w.x, acc[2][0]); acc[2][1] = fmaf(a.z, w.y, acc[2][1]);
            acc[2][2] = fmaf(a.z, w.z, acc[2][2]); acc[2][3] = fmaf(a.z, w.w, acc[2][3]);
            acc[3][0] = fmaf(a.w, w.x, acc[3][0]); acc[3][1] = fmaf(a.w, w.y, acc[3][1]);
            acc[3][2] = fmaf(a.w, w.z, acc[3][2]); acc[3][3] = fmaf(a.w, w.w, acc[3][3]);
        }
        __syncthreads();
    }
    float bo0 = b_out[to + 0], bo1 = b_out[to + 1], bo2 = b_out[to + 2], bo3 = b_out[to + 3];
#pragma unroll
    for (int i = 0; i < 4; i++) {
        float4 r;
        r.x = acc[i][0] + bo0; r.y = acc[i][1] + bo1;
        r.z = acc[i][2] + bo2; r.w = acc[i][3] + bo3;
        *(float4*)(out + ((size_t)b * Tv + t0 + tt + i) * DOUT + to) = r;
    }
}

extern "C" void kernel_launch(void* const* d_in, const int* in_sizes, int n_in,
                              void* d_out, int out_size) {
    (void)in_sizes; (void)n_in; (void)out_size;
    const float* x     = (const float*)d_in[0];
    const float* w_ih1 = (const float*)d_in[1];
    const float* w_hh1 = (const float*)d_in[2];
    const float* b_ih1 = (const float*)d_in[3];
    const float* b_hh1 = (const float*)d_in[4];
    const float* w_ih2 = (const float*)d_in[5];
    const float* w_hh2 = (const float*)d_in[6];
    const float* b_ih2 = (const float*)d_in[7];
    const float* b_hh2 = (const float*)d_in[8];
    const float* w_out = (const float*)d_in[9];
    const float* b_out = (const float*)d_in[10];

    xpose<<<Tv, 256>>>(x);
    cudaFuncSetAttribute(lstm_kernel, cudaFuncAttributeMaxDynamicSharedMemorySize, SMEM_BYTES);
    lstm_kernel<<<NCTA, NTHR, SMEM_BYTES>>>(w_ih1, w_hh1, b_ih1, b_hh1,
                                            w_ih2, w_hh2, b_ih2, b_hh2);
    out_gemm<<<dim3(Tv / 64, Bv), 256>>>(w_out, b_out, (float*)d_out);
}

// round 16
// speedup vs baseline: 1.1103x; 1.1103x over previous
#include <cuda_runtime.h>
#include <cuda_fp16.h>
#include <cstdint>

#define Bv 128
#define Tv 4096
#define DIN 64
#define Hv 512
#define DOUT 64
#define NCTA 128
#define NTHR 320            // 8 compute warps (4/stream) + 2 producer warps
#define K1 576
#define K2 1024
#define K1PH 584            // weight row stride (halfs) -> conflict-free B-frag LDS
#define K2PH 1032
#define NBIG1 5             // L1: 1 x half-chunk + 4 big h-chunks
#define NBIG2 8             // L2: 8 big chunks
#define NRING 4             // per-stream ring of big buffers
#define H1D 8               // h1 ring depth (power of 2)
#define GW 72               // row stride (halfs) -> conflict-free A-frag LDS
#define HC_W (64 * GW)      // half-chunk (64 rows) in halfs
#define HC_BYTES (HC_W * 2)         // 9216
#define BIGH_W (2 * HC_W)           // big chunk (2 chunks, one stream)
#define BIGH_BYTES (2 * HC_BYTES)   // 18432
#define OW 68               // out_gemm smem stride (floats)
#define FLG 64              // flag spacing (words) = 256B
#define SMEM_BYTES (2 * NRING * BIGH_BYTES + 32 * K2PH * 2 + 128 * 8 * 4 + 32 * 4 + 256)

// Persistent scratch (static __device__: the sanctioned allocation path)
__device__ __half g_xT[(size_t)Tv * 2 * HC_W];                   // x: [t][s][64][GW]
__device__ __half g_h1[H1D][2][8][64][GW];                       // h1 ring, stream-major
__device__ __half g_h2all[(size_t)(Tv + 1) * 2 * 8 * HC_W];      // h2: [t][s][ch][64][GW]
__device__ unsigned g_flag[NCTA * 2 * FLG];                      // per-CTA-per-stream flags

__device__ __forceinline__ float sigm(float x) { return 1.0f / (1.0f + __expf(-x)); }
__device__ __forceinline__ float tanh_(float x) { return 1.0f - 2.0f / (__expf(2.0f * x) + 1.0f); }

__device__ __forceinline__ unsigned ld_acq(const unsigned* p) {
    unsigned v;
    asm volatile("ld.acquire.gpu.global.b32 %0, [%1];" : "=r"(v) : "l"(p));
    return v;
}
__device__ __forceinline__ void st_rel(unsigned* p, unsigned v) {
    asm volatile("st.release.gpu.global.b32 [%0], %1;" :: "l"(p), "r"(v) : "memory");
}
__device__ __forceinline__ void flag_spin(const unsigned* p, unsigned tgt) {
    while ((int)(ld_acq(p) - tgt) < 0) {}
}
// poll two flags concurrently (both loads in flight each iteration)
__device__ __forceinline__ void flag_spin2(const unsigned* p0, const unsigned* p1,
                                           unsigned tgt) {
    while (true) {
        unsigned v0 = ld_acq(p0);
        unsigned v1 = ld_acq(p1);
        if ((int)(v0 - tgt) >= 0 && (int)(v1 - tgt) >= 0) break;
    }
}
__device__ __forceinline__ void issue_big(unsigned sdst, const void* gsrc, unsigned mbar,
                                          unsigned bytes) {
    asm volatile("mbarrier.arrive.expect_tx.shared.b64 _, [%0], %1;"
                 :: "r"(mbar), "r"(bytes) : "memory");
    asm volatile("cp.async.bulk.shared::cta.global.mbarrier::complete_tx::bytes [%0], [%1], %2, [%3];"
                 :: "r"(sdst), "l"(gsrc), "r"(bytes), "r"(mbar) : "memory");
}
__device__ __forceinline__ void mbar_wait(unsigned mbar, unsigned parity) {
    asm volatile(
        "{\n\t.reg .pred P;\n"
        "W%=:\n\t"
        "mbarrier.try_wait.parity.acquire.cta.shared::cta.b64 P, [%0], %1, 0x989680;\n\t"
        "@!P bra W%=;\n\t}"
        :: "r"(mbar), "r"(parity) : "memory");
}
__device__ __forceinline__ void mbar_arrive(unsigned mbar) {
    asm volatile("mbarrier.arrive.shared.b64 _, [%0];" :: "r"(mbar) : "memory");
}

// One-time x transpose + fp16 round: x[b][t][64] -> xT[t][stream][64][GW]
__global__ void __launch_bounds__(256)
xpose(const float* __restrict__ x) {
    const int t = blockIdx.x;
    for (int i = threadIdx.x; i < 128 * 16; i += 256) {
        int b = i >> 4, j = i & 15;
        int s = b >> 6, lr = b & 63;
        float4 v = *(const float4*)(x + ((size_t)b * Tv + t) * 64 + j * 4);
        __half2* dst = (__half2*)(g_xT + ((size_t)t * 2 + s) * HC_W + lr * GW + j * 4);
        dst[0] = __floats2half2_rn(v.x, v.y);
        dst[1] = __floats2half2_rn(v.z, v.w);
    }
}

__global__ void __launch_bounds__(NTHR, 1)
lstm_kernel(const float* __restrict__ w_ih1, const float* __restrict__ w_hh1,
            const float* __restrict__ b_ih1, const float* __restrict__ b_hh1,
            const float* __restrict__ w_ih2, const float* __restrict__ w_hh2,
            const float* __restrict__ b_ih2, const float* __restrict__ b_hh2) {
    extern __shared__ __half smh[];
    __half* swh = smh + 2 * NRING * BIGH_W;          // weights fp16 [32][K1PH|K2PH]
    float* sc = (float*)(swh + 32 * K2PH);           // c-state [128][8] (global row)
    float* sb = sc + 128 * 8;                        // fused biases [32]
    float* mbf = sb + 32;                            // full[2][4]@+0 (64B), consumed[2][4]@+64
    __shared__ unsigned s_e0[2];

    const int tid = threadIdx.x;
    const bool isL2 = blockIdx.x >= 64;
    const int cl = blockIdx.x & 63;
    const int u0 = cl * 8;
    const int lane = tid & 31, warp = tid >> 5;
    const int c4 = lane & 3, q = lane >> 2;
    const int KPH = isL2 ? K2PH : K1PH;
    const int NBIG = isL2 ? NBIG2 : NBIG1;
    const unsigned smem_base = (unsigned)__cvta_generic_to_shared(smh);
    const unsigned mb = (unsigned)__cvta_generic_to_shared(mbf);
    const int ch = u0 >> 6, colbase = u0 & 63;

    if (tid == 0) {
        s_e0[0] = ld_acq(&g_flag[(blockIdx.x * 2 + 0) * FLG]);
        s_e0[1] = ld_acq(&g_flag[(blockIdx.x * 2 + 1) * FLG]);
#pragma unroll
        for (int b = 0; b < 2 * NRING; b++) {
            asm volatile("mbarrier.init.shared.b64 [%0], 1;" :: "r"(mb + b * 8) : "memory");
            asm volatile("mbarrier.init.shared.b64 [%0], 4;" :: "r"(mb + 64 + b * 8) : "memory");
        }
        asm volatile("fence.proxy.async.shared::cta;" ::: "memory");
    }

    // ---- stage weight slice (fp16) + fused biases ----
    if (!isL2) {
        for (int idx = tid; idx < 32 * K1; idx += NTHR) {
            int r = idx / K1, k = idx - r * K1;
            int j = (r >> 3) * Hv + u0 + (r & 7);
            float wv = (k < DIN) ? w_ih1[j * DIN + k] : w_hh1[(size_t)j * Hv + (k - DIN)];
            swh[r * K1PH + k] = __float2half_rn(wv);
        }
        if (tid < 32) {
            int j = (tid >> 3) * Hv + u0 + (tid & 7);
            sb[tid] = b_ih1[j] + b_hh1[j];
        }
    } else {
        for (int idx = tid; idx < 32 * K2; idx += NTHR) {
            int r = idx >> 10, k = idx & 1023;
            int j = (r >> 3) * Hv + u0 + (r & 7);
            float wv = (k < Hv) ? w_ih2[(size_t)j * Hv + k] : w_hh2[(size_t)j * Hv + (k - Hv)];
            swh[r * K2PH + k] = __float2half_rn(wv);
        }
        if (tid < 32) {
            int j = (tid >> 3) * Hv + u0 + (tid & 7);
            sb[tid] = b_ih2[j] + b_hh2[j];
        }
    }
    for (int i = tid; i < 128 * 8; i += NTHR) sc[i] = 0.0f;

    // ---- zero OWN slice of initial state: h1 ring slot H1D-1 / h2 slot 0 ----
    if (tid < 128) {
        __half z[8];
#pragma unroll
        for (int i = 0; i < 8; i++) z[i] = __float2half(0.0f);
        int s = tid >> 6, lr = tid & 63;
        __half* dst = isL2
            ? g_h2all + (size_t)s * 8 * HC_W + ch * HC_W + lr * GW + colbase
            : &g_h1[H1D - 1][s][ch][lr][colbase];
        *(uint4*)dst = *(const uint4*)z;
    }
    __syncthreads();
    if (tid == 0) {
        __threadfence();
        st_rel(&g_flag[(blockIdx.x * 2 + 0) * FLG], s_e0[0] + 1);
        st_rel(&g_flag[(blockIdx.x * 2 + 1) * FLG], s_e0[1] + 1);
    }
    __syncthreads();   // all threads see s_e0

    if (warp >= 8) {
        // ================= PRODUCER WARPS (8: stream 0, 9: stream 1) =================
        const int s = warp - 8;
        const unsigned E0 = s_e0[s];
        const unsigned fullb0 = mb + s * NRING * 8;
        const unsigned consb0 = mb + 64 + s * NRING * 8;
        const unsigned cbase = smem_base + s * NRING * BIGH_BYTES;
        unsigned gidx = 0;
        for (int p = 0; p <= Tv; p++) {
            const bool active = isL2 ? (p >= 1) : (p < Tv);
            if (!active) continue;
            const unsigned T = E0 + (unsigned)p + 1u;
            if (!isL2 && p >= 6) {   // slack: keep L1 bounded ahead of L2 (own stream)
                const unsigned ts = E0 + (unsigned)p - 5u;
                for (int k = lane; k < 64; k += 32)
                    flag_spin(&g_flag[((64 + k) * 2 + s) * FLG], ts);
                __syncwarp();
            }
            if (!isL2) {
                const __half* srcA = g_xT + ((size_t)p * 2 + s) * HC_W;
                const __half* srcB = &g_h1[(p - 1) & (H1D - 1)][s][0][0][0];
                // chunk 0 (x): no data deps, issue immediately
                {
                    const unsigned sl = gidx & (NRING - 1), m = gidx >> 2;
                    if (lane == 0) {
                        if (m >= 1) mbar_wait(consb0 + sl * 8, (m - 1) & 1u);
                        issue_big(cbase + sl * BIGH_BYTES, srcA, fullb0 + sl * 8, HC_BYTES);
                    }
                    __syncwarp();
                    gidx++;
                }
                // one wide poll: all 64 h1-producer flags (2 per lane, concurrent)
                flag_spin2(&g_flag[(lane * 2 + s) * FLG],
                           &g_flag[((lane + 32) * 2 + s) * FLG], T);
                __syncwarp();
                for (int b = 1; b < NBIG1; b++) {
                    const __half* src = srcB + (size_t)(b - 1) * BIGH_W;
                    const unsigned sl = gidx & (NRING - 1), m = gidx >> 2;
                    if (lane == 0) {
                        if (m >= 1) mbar_wait(consb0 + sl * 8, (m - 1) & 1u);
                        issue_big(cbase + sl * BIGH_BYTES, src, fullb0 + sl * 8, BIGH_BYTES);
                    }
                    __syncwarp();
                    gidx++;
                }
            } else {
                const __half* srcA = &g_h1[(p - 1) & (H1D - 1)][s][0][0][0];
                const __half* srcB = g_h2all + ((size_t)(p - 1) * 2 + s) * 8 * HC_W;
                // wide poll: 64 h1 flags (CTAs 0..63)
                flag_spin2(&g_flag[(lane * 2 + s) * FLG],
                           &g_flag[((lane + 32) * 2 + s) * FLG], T);
                __syncwarp();
                for (int b = 0; b < 4; b++) {
                    const __half* src = srcA + (size_t)b * BIGH_W;
                    const unsigned sl = gidx & (NRING - 1), m = gidx >> 2;
                    if (lane == 0) {
                        if (m >= 1) mbar_wait(consb0 + sl * 8, (m - 1) & 1u);
                        issue_big(cbase + sl * BIGH_BYTES, src, fullb0 + sl * 8, BIGH_BYTES);
                    }
                    __syncwarp();
                    gidx++;
                }
                // wide poll: 64 h2 flags (CTAs 64..127)
                flag_spin2(&g_flag[((64 + lane) * 2 + s) * FLG],
                           &g_flag[((96 + lane) * 2 + s) * FLG], T);
                __syncwarp();
                for (int b = 4; b < NBIG2; b++) {
                    const __half* src = srcB + (size_t)(b - 4) * BIGH_W;
                    const unsigned sl = gidx & (NRING - 1), m = gidx >> 2;
                    if (lane == 0) {
                        if (m >= 1) mbar_wait(consb0 + sl * 8, (m - 1) & 1u);
                        issue_big(cbase + sl * BIGH_BYTES, src, fullb0 + sl * 8, BIGH_BYTES);
                    }
                    __syncwarp();
                    gidx++;
                }
            }
        }
    } else {
        // ================= COMPUTE WARPS: 0-3 stream 0, 4-7 stream 1 =================
        const int s = warp >> 2;
        const unsigned E0 = s_e0[s];
        const int wl = warp & 3;
        const int r0 = wl * 16 + q, r1 = r0 + 8;     // rows within 64-row half
        const unsigned fullb0 = mb + s * NRING * 8;
        const unsigned consb0 = mb + 64 + s * NRING * 8;
        __half* chunks = smh + s * NRING * BIGH_W;
        unsigned* myflag = &g_flag[(blockIdx.x * 2 + s) * FLG];
        unsigned phbits = 0, gidx = 0;
        for (int p = 0; p <= Tv; p++) {
            const bool active = isL2 ? (p >= 1) : (p < Tv);
            if (active) {
                float acc[4][4];
#pragma unroll
                for (int g = 0; g < 4; g++) {
                    float b0 = sb[g * 8 + 2 * c4], b1 = sb[g * 8 + 2 * c4 + 1];
                    acc[g][0] = b0; acc[g][1] = b1; acc[g][2] = b0; acc[g][3] = b1;
                }
                for (int b = 0; b < NBIG; b++) {
                    const unsigned sl = gidx & (NRING - 1);
                    mbar_wait(fullb0 + sl * 8, (phbits >> sl) & 1u);
                    phbits ^= (1u << sl);

                    const int nsub = (isL2 || b > 0) ? 2 : 1;
                    const int kbb = isL2 ? b * 128 : (b == 0 ? 0 : 64 + (b - 1) * 128);
                    for (int s2 = 0; s2 < nsub; s2++) {
                        const __half* ar0 = chunks + sl * BIGH_W + s2 * HC_W
                                          + r0 * GW + 2 * c4;
                        const __half* ar1 = chunks + sl * BIGH_W + s2 * HC_W
                                          + r1 * GW + 2 * c4;
                        const int kb = kbb + s2 * 64;
#pragma unroll
                        for (int kc = 0; kc < 64; kc += 16) {
                            unsigned a0 = *(const unsigned*)(ar0 + kc);
                            unsigned a1 = *(const unsigned*)(ar1 + kc);
                            unsigned a2 = *(const unsigned*)(ar0 + kc + 8);
                            unsigned a3 = *(const unsigned*)(ar1 + kc + 8);
#pragma unroll
                            for (int g = 0; g < 4; g++) {
                                const __half* bp = swh + (g * 8 + q) * KPH + kb + kc + 2 * c4;
                                unsigned b0 = *(const unsigned*)bp;
                                unsigned b1 = *(const unsigned*)(bp + 8);
                                asm volatile(
                                    "mma.sync.aligned.m16n8k16.row.col.f32.f16.f16.f32 "
                                    "{%0,%1,%2,%3},{%4,%5,%6,%7},{%8,%9},{%0,%1,%2,%3};"
                                    : "+f"(acc[g][0]), "+f"(acc[g][1]),
                                      "+f"(acc[g][2]), "+f"(acc[g][3])
                                    : "r"(a0), "r"(a1), "r"(a2), "r"(a3), "r"(b0), "r"(b1));
                            }
                        }
                    }
                    if (lane == 0) mbar_arrive(consb0 + sl * 8);
                    gidx++;
                }

                // ---- epilogue: nonlinearities, c update (SMEM), fp16 h store ----
                __half* hout = isL2
                    ? g_h2all + ((size_t)p * 2 + s) * 8 * HC_W + ch * HC_W + colbase
                    : &g_h1[p & (H1D - 1)][s][ch][0][colbase];
#pragma unroll
                for (int jj = 0; jj < 2; jj++) {
                    int ul = 2 * c4 + jj;
#pragma unroll
                    for (int rr = 0; rr < 2; rr++) {
                        int lr = rr ? r1 : r0;
                        int qi = rr * 2 + jj;
                        float iv = sigm(acc[0][qi]);
                        float fv = sigm(acc[1][qi]);
                        float gv = tanh_(acc[2][qi]);
                        float ov = sigm(acc[3][qi]);
                        int grow = s * 64 + lr;
                        float cn = fv * sc[grow * 8 + ul] + iv * gv;
                        sc[grow * 8 + ul] = cn;
                        hout[(size_t)lr * GW + ul] = __float2half_rn(ov * tanh_(cn));
                    }
                }
            }
            // per-stream compute barrier (128 threads), then publish stream flag
            if (s == 0) asm volatile("bar.sync 1, 128;" ::: "memory");
            else        asm volatile("bar.sync 2, 128;" ::: "memory");
            if (wl == 0 && lane == 0) {
                __threadfence();
                st_rel(myflag, E0 + (unsigned)p + 2u);
            }
        }
    }
}

// Post-pass: out[b][t][o] = h2(t)[b] . w_out[o] + b_out[o]
__global__ void __launch_bounds__(256)
out_gemm(const float* __restrict__ w_out, const float* __restrict__ b_out,
         float* __restrict__ out) {
    __shared__ __align__(16) float As[32 * OW];  // [k][t]
    __shared__ __align__(16) float Bs[32 * OW];  // [k][o]
    const int b = blockIdx.y;
    const int t0 = blockIdx.x * 64;
    const int tx = threadIdx.x;
    const int to = (tx & 15) * 4;
    const int tt = (tx >> 4) * 4;
    const int bs = b >> 6, blr = b & 63;
    float acc[4][4] = {};
    for (int k0 = 0; k0 < Hv; k0 += 32) {
        for (int i = tx; i < 512; i += 256) {
            int row = i >> 3, kq = (i & 7) * 4;
            const __half* src = g_h2all + ((size_t)(t0 + row + 1) * 2 + bs) * 8 * HC_W
                              + (k0 >> 6) * HC_W + (size_t)blr * GW + (k0 & 63) + kq;
            float2 f0 = __half22float2(*(const __half2*)(src));
            float2 f1 = __half22float2(*(const __half2*)(src + 2));
            As[(kq + 0) * OW + row] = f0.x;
            As[(kq + 1) * OW + row] = f0.y;
            As[(kq + 2) * OW + row] = f1.x;
            As[(kq + 3) * OW + row] = f1.y;
        }
        for (int i = tx; i < 512; i += 256) {
            int o = i >> 3, kq = (i & 7) * 4;
            float4 v = *(const float4*)(w_out + (size_t)o * Hv + k0 + kq);
            Bs[(kq + 0) * OW + o] = v.x;
            Bs[(kq + 1) * OW + o] = v.y;
            Bs[(kq + 2) * OW + o] = v.z;
            Bs[(kq + 3) * OW + o] = v.w;
        }
        __syncthreads();
#pragma unroll
        for (int k = 0; k < 32; k++) {
            float4 a = *(const float4*)(As + k * OW + tt);
            float4 w = *(const float4*)(Bs + k * OW + to);
            acc[0][0] = fmaf(a.x, w.x, acc[0][0]); acc[0][1] = fmaf(a.x, w.y, acc[0][1]);
            acc[0][2] = fmaf(a.x, w.z, acc[0][2]); acc[0][3] = fmaf(a.x, w.w, acc[0][3]);
            acc[1][0] = fmaf(a.y, w.x, acc[1][0]); acc[1][1] = fmaf(a.y, w.y, acc[1][1]);
            acc[1][2] = fmaf(a.y, w.z, acc[1][2]); acc[1][3] = fmaf(a.y, w.w, acc[1][3]);
            acc[2][0] = fmaf(a.z, w.x, acc[2][0]); acc[2][1] = fmaf(a.z, w.y, acc[2][1]);
            acc[2][2] = fmaf(a.z, w.z, acc[2][2]); acc[2][3] = fmaf(a.z, w.w, acc[2][3]);
            acc[3][0] = fmaf(a.w, w.x, acc[3][0]); acc[3][1] = fmaf(a.w, w.y, acc[3][1]);
            acc[3][2] = fmaf(a.w, w.z, acc[3][2]); acc[3][3] = fmaf(a.w, w.w, acc[3][3]);
        }
        __syncthreads();
    }
    float bo0 = b_out[to + 0], bo1 = b_out[to + 1], bo2 = b_out[to + 2], bo3 = b_out[to + 3];
#pragma unroll
    for (int i = 0; i < 4; i++) {
        float4 r;
        r.x = acc[i][0] + bo0; r.y = acc[i][1] + bo1;
        r.z = acc[i][2] + bo2; r.w = acc[i][3] + bo3;
        *(float4*)(out + ((size_t)b * Tv + t0 + tt + i) * DOUT + to) = r;
    }
}

extern "C" void kernel_launch(void* const* d_in, const int* in_sizes, int n_in,
                              void* d_out, int out_size) {
    (void)in_sizes; (void)n_in; (void)out_size;
    const float* x     = (const float*)d_in[0];
    const float* w_ih1 = (const float*)d_in[1];
    const float* w_hh1 = (const float*)d_in[2];
    const float* b_ih1 = (const float*)d_in[3];
    const float* b_hh1 = (const float*)d_in[4];
    const float* w_ih2 = (const float*)d_in[5];
    const float* w_hh2 = (const float*)d_in[6];
    const float* b_ih2 = (const float*)d_in[7];
    const float* b_hh2 = (const float*)d_in[8];
    const float* w_out = (const float*)d_in[9];
    const float* b_out = (const float*)d_in[10];

    xpose<<<Tv, 256>>>(x);
    cudaFuncSetAttribute(lstm_kernel, cudaFuncAttributeMaxDynamicSharedMemorySize, SMEM_BYTES);
    lstm_kernel<<<NCTA, NTHR, SMEM_BYTES>>>(w_ih1, w_hh1, b_ih1, b_hh1,
                                            w_ih2, w_hh2, b_ih2, b_hh2);
    out_gemm<<<dim3(Tv / 64, Bv), 256>>>(w_out, b_out, (float*)d_out);
}